// round 9
// baseline (speedup 1.0000x reference)
#include <cuda_runtime.h>

// B=8, MSP=2048, D=512, A=64, NB=5
// Exact contraction reordering:
//   Wc[n,d]   = W_fl[n,d] + W_fl[n,512+d]
//   S[n]      = sum_d Wc[n,d]
//   t[b,s,n]  = sum_d e[b,s,d] * Wc[n,d]
//   out[b,a,n]= sum_s W_ll[a,s] * t[b,s,n] + b_ll[a]*S[n] + b_fl[n]
//   final[b,i,j,n] = out[b,i,n]
//
// SINGLE kernel. 256 blocks x 256 threads: block = (b, 64-s slice).
// Each warp: 8 rows; per row compute t[s,:] (FFMA2 + butterfly) and fold
// into per-lane register accumulators for a=lane / a=lane+32, with W_ll
// read from a conflict-free transposed smem tile (fixes the R8 gather).
// Block epilogue: smem-combine 8 warps, 320 atomicAdds into g_out2[b].
// Last-of-32 block per b (ticket) finalizes: biases + 80 KB broadcast
// write + reset of g_out2/ticket for the next graph replay.

#define DVAL   512
#define NB     5
#define AVAL   64
#define BVAL   8
#define MSP    2048
#define GRID   256            // 8 b x 32 s-slices
#define TPB    256
#define SPB    64             // s per block
#define SPW    8              // s per warp

__device__ float g_out2[BVAL * AVAL * NB];   // 2560 floats, zero at launch entry
__device__ int   g_tick[BVAL];               // per-b completion tickets

// Packed f32x2 FMA (Blackwell)
__device__ __forceinline__ unsigned long long fma2(unsigned long long a,
                                                   unsigned long long b,
                                                   unsigned long long c) {
    unsigned long long d;
    asm("fma.rn.f32x2 %0, %1, %2, %3;" : "=l"(d) : "l"(a), "l"(b), "l"(c));
    return d;
}
__device__ __forceinline__ float unpack_add(unsigned long long v) {
    float lo, hi;
    asm("mov.b64 {%0, %1}, %2;" : "=f"(lo), "=f"(hi) : "l"(v));
    return lo + hi;
}

__global__ __launch_bounds__(TPB, 2) void fused_kernel(const float* __restrict__ e,
                                                       const float* __restrict__ W_fl,
                                                       const float* __restrict__ W_ll,
                                                       const float* __restrict__ b_ll,
                                                       const float* __restrict__ b_fl,
                                                       float* __restrict__ out) {
    __shared__ __align__(16) float wcs[NB * DVAL];     // 10 KB
    __shared__ float wllT[SPB * 65];                   // 16.25 KB, pad-65
    __shared__ float sacc[8][AVAL * NB];               // 10 KB
    __shared__ float sS[NB];
    __shared__ float vfin[AVAL * NB];                  // finisher values
    __shared__ int   my_ticket;

    const int tid  = threadIdx.x;
    const int lane = tid & 31;
    const int warp = tid >> 5;
    const int b    = blockIdx.x >> 5;          // 0..7
    const int sblk = blockIdx.x & 31;          // 0..31
    const int s0b  = sblk * SPB;

    // ---- stage Wc ----
    for (int i = tid; i < NB * DVAL; i += TPB) {
        int n = i / DVAL, d = i - n * DVAL;
        wcs[i] = W_fl[n * 1024 + d] + W_fl[n * 1024 + 512 + d];
    }
    // ---- stage W_ll tile transposed: wllT[sl][a], conflict-free pad ----
    for (int i = tid; i < AVAL * SPB; i += TPB) {
        int a = i >> 6, sl = i & 63;           // consecutive tid -> consecutive sl (coalesced LDG)
        wllT[sl * 65 + a] = W_ll[(size_t)a * MSP + s0b + sl];
    }
    __syncthreads();

    // ---- every block computes S (warp 0) ----
    if (warp == 0) {
        #pragma unroll
        for (int n = 0; n < NB; n++) {
            float s = 0.f;
            for (int d = lane; d < DVAL; d += 32) s += wcs[n * DVAL + d];
            #pragma unroll
            for (int off = 16; off > 0; off >>= 1)
                s += __shfl_xor_sync(0xFFFFFFFFu, s, off);
            if (lane == 0) sS[n] = s;
        }
    }

    // ---- per-lane Wc as packed f32x2: lane owns d = r*128 + lane*4 .. +3 ----
    ulonglong2 wc2[4][NB];
    #pragma unroll
    for (int r = 0; r < 4; r++)
        #pragma unroll
        for (int n = 0; n < NB; n++)
            wc2[r][n] = *(const ulonglong2*)&wcs[n * DVAL + r * 128 + lane * 4];

    // ---- main loop: 8 rows per warp, pipelined ----
    const int slw = warp * SPW;                           // local s base
    const float* ebase = e + ((size_t)b * MSP + s0b + slw) * DVAL;

    float accA0[NB], accA1[NB];
    #pragma unroll
    for (int n = 0; n < NB; n++) { accA0[n] = 0.f; accA1[n] = 0.f; }

    ulonglong2 ev[4];
    {
        const ulonglong2* er = (const ulonglong2*)ebase;
        #pragma unroll
        for (int r = 0; r < 4; r++) ev[r] = er[r * 32 + lane];
    }

    #pragma unroll
    for (int i = 0; i < SPW; i++) {
        ulonglong2 ev2[4];
        if (i + 1 < SPW) {
            const ulonglong2* er2 = (const ulonglong2*)(ebase + (size_t)(i + 1) * DVAL);
            #pragma unroll
            for (int r = 0; r < 4; r++) ev2[r] = er2[r * 32 + lane];
        }

        unsigned long long acc2[NB];
        #pragma unroll
        for (int n = 0; n < NB; n++) acc2[n] = 0ull;
        #pragma unroll
        for (int r = 0; r < 4; r++) {
            #pragma unroll
            for (int n = 0; n < NB; n++) {
                acc2[n] = fma2(ev[r].x, wc2[r][n].x, acc2[n]);
                acc2[n] = fma2(ev[r].y, wc2[r][n].y, acc2[n]);
            }
        }

        float t[NB];
        #pragma unroll
        for (int n = 0; n < NB; n++) t[n] = unpack_add(acc2[n]);
        #pragma unroll
        for (int n = 0; n < NB; n++) {
            #pragma unroll
            for (int off = 16; off > 0; off >>= 1)
                t[n] += __shfl_xor_sync(0xFFFFFFFFu, t[n], off);
        }

        // W_ll from transposed smem tile: conflict-free, no gather
        const float wl0 = wllT[(slw + i) * 65 + lane];
        const float wl1 = wllT[(slw + i) * 65 + 32 + lane];
        #pragma unroll
        for (int n = 0; n < NB; n++) {
            accA0[n] += wl0 * t[n];
            accA1[n] += wl1 * t[n];
        }

        #pragma unroll
        for (int r = 0; r < 4; r++) ev[r] = ev2[r];
    }

    // ---- epilogue: combine 8 warps, one atomicAdd per element per block ----
    {
        float* sp = sacc[warp];
        #pragma unroll
        for (int n = 0; n < NB; n++) {
            sp[lane * NB + n]        = accA0[n];     // stride-5: conflict-free
            sp[(lane + 32) * NB + n] = accA1[n];
        }
    }
    __syncthreads();
    for (int idx = tid; idx < AVAL * NB; idx += TPB) {
        float sum = 0.f;
        #pragma unroll
        for (int w = 0; w < 8; w++) sum += sacc[w][idx];
        atomicAdd(&g_out2[b * (AVAL * NB) + idx], sum);
    }

    // ---- ticket: last of the 32 blocks of this b finalizes ----
    __threadfence();
    __syncthreads();
    if (tid == 0) my_ticket = atomicAdd(&g_tick[b], 1);
    __syncthreads();
    if (my_ticket != 31) return;

    // Finisher: read partials (volatile; all 32 blocks' REDGs are fenced
    // before their ticket increment), add biases, reset table for replay.
    {
        volatile float* gp = &g_out2[b * (AVAL * NB)];
        for (int idx = tid; idx < AVAL * NB; idx += TPB) {
            const int a = idx / NB, n = idx - a * NB;
            float x = gp[idx];
            vfin[idx] = x + b_ll[a] * sS[n] + b_fl[n];
            gp[idx] = 0.f;                        // reset for next replay
        }
        if (tid == 0) g_tick[b] = 0;              // reset ticket
    }
    __syncthreads();

    // Broadcast write of this b's slab: 64 i x 64 j x 5 n = 20480 floats.
    // Build per-i 20-float (5x float4) repeating pattern in smem, then
    // stream 5120 float4s with 256 threads (20 each).
    __shared__ __align__(16) float pat[AVAL * 20];       // 5 KB
    for (int i = tid; i < AVAL * 20; i += TPB)
        pat[i] = vfin[(i / 20) * NB + (i % NB)];
    __syncthreads();

    float4* ob = (float4*)(out + (size_t)b * AVAL * AVAL * NB);
    const float4* p4 = (const float4*)pat;
    for (int g = tid; g < AVAL * 80; g += TPB) {
        const int i = g / 80;                     // row i
        ob[g] = p4[i * 5 + (g % 80) % 5];
    }
}

// ---------------------------------------------------------------------------
extern "C" void kernel_launch(void* const* d_in, const int* in_sizes, int n_in,
                              void* d_out, int out_size) {
    const float* e    = (const float*)d_in[0];
    const float* W_ll = (const float*)d_in[1];
    const float* b_ll = (const float*)d_in[2];
    const float* W_fl = (const float*)d_in[3];
    const float* b_fl = (const float*)d_in[4];
    float* out = (float*)d_out;

    fused_kernel<<<GRID, TPB>>>(e, W_fl, W_ll, b_ll, b_fl, out);
}